// round 1
// baseline (speedup 1.0000x reference)
#include <cuda_runtime.h>

#define T_DIM  128
#define B_DIM  64
#define IN_DIM 144          // IN*ND = 48*3
#define H_DIM  2048
#define C_DIM  10
#define BN_EPS 1e-5f
#define MTOT   (T_DIM*B_DIM)        // 8192 rows

// ---------------- scratch (device globals: allocation-free) ----------------
__device__ float g_z[T_DIM*B_DIM*H_DIM];     // 64 MB  pre-activation
__device__ float g_h[T_DIM*B_DIM*H_DIM];     // 64 MB  post-scan hidden
__device__ float g_psum[B_DIM*H_DIM];        // per-(b,h) partial sums
__device__ float g_psumsq[B_DIM*H_DIM];
__device__ float g_scale[H_DIM];             // BN folded affine: h*scale+shift
__device__ float g_shift[H_DIM];

// ---------------- GEMM: Z[m,n] = sum_k A'[m,k]*W[n,k] + bias[n] ------------
// A' = A*scale[k]+shift[k] if scale != nullptr (fused BN of previous layer)
// M=8192 fixed, N=2048 fixed, K = 144 or 2048 (both % 16 == 0)
__global__ __launch_bounds__(256, 2)
void gemm_bias(const float* __restrict__ A, const float* __restrict__ W,
               const float* __restrict__ bias,
               const float* __restrict__ scale, const float* __restrict__ shift,
               float* __restrict__ Z, int K)
{
    __shared__ float As[16][132];   // transposed tiles, +4 pad (16B-aligned rows)
    __shared__ float Bs[16][132];

    const int tid = threadIdx.x;
    const int m0  = blockIdx.y * 128;
    const int n0  = blockIdx.x * 128;
    const int tx  = tid & 15;        // N direction (16)
    const int ty  = tid >> 4;        // M direction (16)

    float acc[8][8] = {};

    for (int k0 = 0; k0 < K; k0 += 16) {
        // cooperative load: 128 rows x 16 k each for A and W, 2 float4/thread
        #pragma unroll
        for (int i = 0; i < 2; ++i) {
            const int f   = tid + i * 256;       // 0..511
            const int row = f >> 2;              // 0..127
            const int kg  = f & 3;               // float4 group within 16 k
            const int kk  = k0 + kg * 4;

            float4 v = *reinterpret_cast<const float4*>(&A[(size_t)(m0 + row) * K + kk]);
            if (scale) {
                const float4 s  = *reinterpret_cast<const float4*>(&scale[kk]);
                const float4 sh = *reinterpret_cast<const float4*>(&shift[kk]);
                v.x = fmaf(v.x, s.x, sh.x);
                v.y = fmaf(v.y, s.y, sh.y);
                v.z = fmaf(v.z, s.z, sh.z);
                v.w = fmaf(v.w, s.w, sh.w);
            }
            As[kg*4+0][row] = v.x;
            As[kg*4+1][row] = v.y;
            As[kg*4+2][row] = v.z;
            As[kg*4+3][row] = v.w;

            const float4 w = *reinterpret_cast<const float4*>(&W[(size_t)(n0 + row) * K + kk]);
            Bs[kg*4+0][row] = w.x;
            Bs[kg*4+1][row] = w.y;
            Bs[kg*4+2][row] = w.z;
            Bs[kg*4+3][row] = w.w;
        }
        __syncthreads();

        #pragma unroll
        for (int kk = 0; kk < 16; ++kk) {
            float a[8], b[8];
            *reinterpret_cast<float4*>(&a[0]) = *reinterpret_cast<const float4*>(&As[kk][ty*8]);
            *reinterpret_cast<float4*>(&a[4]) = *reinterpret_cast<const float4*>(&As[kk][ty*8+4]);
            *reinterpret_cast<float4*>(&b[0]) = *reinterpret_cast<const float4*>(&Bs[kk][tx*8]);
            *reinterpret_cast<float4*>(&b[4]) = *reinterpret_cast<const float4*>(&Bs[kk][tx*8+4]);
            #pragma unroll
            for (int i = 0; i < 8; ++i)
                #pragma unroll
                for (int j = 0; j < 8; ++j)
                    acc[i][j] = fmaf(a[i], b[j], acc[i][j]);
        }
        __syncthreads();
    }

    // epilogue: + bias, vectorized store
    #pragma unroll
    for (int i = 0; i < 8; ++i) {
        const int m = m0 + ty * 8 + i;
        float* zrow = &Z[(size_t)m * H_DIM + n0 + tx * 8];
        #pragma unroll
        for (int j = 0; j < 8; j += 4) {
            const int n = n0 + tx * 8 + j;
            float4 r;
            r.x = acc[i][j+0] + bias[n+0];
            r.y = acc[i][j+1] + bias[n+1];
            r.z = acc[i][j+2] + bias[n+2];
            r.w = acc[i][j+3] + bias[n+3];
            *reinterpret_cast<float4*>(&zrow[j]) = r;
        }
    }
}

// ---------------- IndRNN scan: h_t = relu(z_t + u*h_{t-1}) -----------------
// One thread per (b,h). Also emits per-thread sum / sumsq for BN stats
// (deterministic — no atomics).
__global__ __launch_bounds__(256)
void scan_kernel(const float* __restrict__ Z, const float* __restrict__ u,
                 float* __restrict__ Hout,
                 float* __restrict__ psum, float* __restrict__ psumsq)
{
    const int j  = blockIdx.x * blockDim.x + threadIdx.x;   // 0..B*H-1
    const float uh = u[j & (H_DIM - 1)];
    const int BH = B_DIM * H_DIM;

    float hc = 0.0f, s = 0.0f, s2 = 0.0f;
    #pragma unroll 4
    for (int t = 0; t < T_DIM; ++t) {
        const float v = Z[(size_t)t * BH + j];
        hc = fmaxf(fmaf(uh, hc, v), 0.0f);
        Hout[(size_t)t * BH + j] = hc;
        s  += hc;
        s2 = fmaf(hc, hc, s2);
    }
    psum[j]   = s;
    psumsq[j] = s2;
}

// ---------------- BN stats finalize -> folded affine (scale, shift) --------
__global__ __launch_bounds__(256)
void bn_finalize(const float* __restrict__ psum, const float* __restrict__ psumsq,
                 const float* __restrict__ gamma, const float* __restrict__ beta,
                 float* __restrict__ scale, float* __restrict__ shift)
{
    const int h = blockIdx.x * blockDim.x + threadIdx.x;    // < H
    float s = 0.0f, s2 = 0.0f;
    #pragma unroll 8
    for (int b = 0; b < B_DIM; ++b) {
        s  += psum[b * H_DIM + h];
        s2 += psumsq[b * H_DIM + h];
    }
    const float inv_n = 1.0f / (float)(T_DIM * B_DIM);
    const float mean  = s * inv_n;
    const float var   = s2 * inv_n - mean * mean;
    const float rstd  = rsqrtf(var + BN_EPS);
    const float sc    = gamma[h] * rstd;
    scale[h] = sc;
    shift[h] = fmaf(-mean, sc, beta[h]);
}

// ---------------- final projection: out[b,c] = BN(h[T-1,b]) . Wlast[c] -----
__global__ __launch_bounds__(256)
void final_proj(const float* __restrict__ Hlast,
                const float* __restrict__ scale, const float* __restrict__ shift,
                const float* __restrict__ Wl, const float* __restrict__ bl,
                float* __restrict__ out)
{
    const int b = blockIdx.x;    // 0..63
    const int c = blockIdx.y;    // 0..9
    __shared__ float red[256];

    float s = 0.0f;
    for (int h = threadIdx.x; h < H_DIM; h += 256) {
        const float hn = fmaf(Hlast[b * H_DIM + h], scale[h], shift[h]);
        s = fmaf(hn, Wl[c * H_DIM + h], s);
    }
    red[threadIdx.x] = s;
    __syncthreads();
    for (int off = 128; off > 0; off >>= 1) {
        if (threadIdx.x < off) red[threadIdx.x] += red[threadIdx.x + off];
        __syncthreads();
    }
    if (threadIdx.x == 0) out[b * C_DIM + c] = red[0] + bl[c];
}

// ---------------- launcher -------------------------------------------------
extern "C" void kernel_launch(void* const* d_in, const int* in_sizes, int n_in,
                              void* d_out, int out_size)
{
    const float* x      = (const float*)d_in[0];   // [T,B,IN,ND] = [8192,144]
    const float* W0     = (const float*)d_in[1];   // [H,144]
    const float* Ws     = (const float*)d_in[2];   // [3,H,H]
    const float* bs     = (const float*)d_in[3];   // [L,H]
    const float* us     = (const float*)d_in[4];   // [L,H]
    const float* gammas = (const float*)d_in[5];   // [L,H]
    const float* betas  = (const float*)d_in[6];   // [L,H]
    const float* Wlast  = (const float*)d_in[7];   // [C,H]
    const float* blast  = (const float*)d_in[8];   // [C]
    float* out = (float*)d_out;

    float *z, *h, *psum, *psumsq, *scale, *shift;
    cudaGetSymbolAddress((void**)&z,      g_z);
    cudaGetSymbolAddress((void**)&h,      g_h);
    cudaGetSymbolAddress((void**)&psum,   g_psum);
    cudaGetSymbolAddress((void**)&psumsq, g_psumsq);
    cudaGetSymbolAddress((void**)&scale,  g_scale);
    cudaGetSymbolAddress((void**)&shift,  g_shift);

    const dim3 ggrid(H_DIM / 128, MTOT / 128);   // 16 x 64 blocks

    for (int l = 0; l < 4; ++l) {
        const float* A  = (l == 0) ? x  : h;
        const float* W  = (l == 0) ? W0 : Ws + (size_t)(l - 1) * H_DIM * H_DIM;
        const int    K  = (l == 0) ? IN_DIM : H_DIM;
        const float* sc = (l == 0) ? nullptr : scale;
        const float* sh = (l == 0) ? nullptr : shift;

        gemm_bias<<<ggrid, 256>>>(A, W, bs + l * H_DIM, sc, sh, z, K);
        scan_kernel<<<(B_DIM * H_DIM) / 256, 256>>>(z, us + l * H_DIM, h, psum, psumsq);
        bn_finalize<<<H_DIM / 256, 256>>>(psum, psumsq,
                                          gammas + l * H_DIM, betas + l * H_DIM,
                                          scale, shift);
    }

    final_proj<<<dim3(B_DIM, C_DIM), 256>>>(h + (size_t)(T_DIM - 1) * B_DIM * H_DIM,
                                            scale, shift, Wlast, blast, out);
}

// round 3
// speedup vs baseline: 2.9406x; 2.9406x over previous
#include <cuda_runtime.h>
#include <cuda_bf16.h>
#include <cstdint>

#define T_DIM  128
#define B_DIM  64
#define IN_RAW 144           // IN*ND
#define K0_PAD 192           // layer-0 K padded to multiple of 64
#define H_DIM  2048
#define C_DIM  10
#define BN_EPS 1e-5f
#define MTOT   (T_DIM*B_DIM) // 8192
#define BH     (B_DIM*H_DIM)

// GEMM tile config
#define BM 128
#define BN 128
#define KC 64                              // bf16 per chunk = one 128B smem row
#define TILE_BYTES 16384                   // 128 rows x 128 B
#define STAGE_BYTES (4*TILE_BYTES)         // Ah, Al, Bh, Bl
#define NSTAGE 3
#define DSMEM_BYTES (NSTAGE*STAGE_BYTES + 1024)

// ---------------- scratch ----------------
__device__ float         g_z[MTOT*H_DIM];      // 64MB
__device__ __nv_bfloat16 g_ah[MTOT*H_DIM];     // 32MB
__device__ __nv_bfloat16 g_al[MTOT*H_DIM];     // 32MB
__device__ __nv_bfloat16 g_wh[H_DIM*H_DIM];    // 8MB
__device__ __nv_bfloat16 g_wl[H_DIM*H_DIM];    // 8MB
__device__ float         g_biasadj[H_DIM];
__device__ float         g_psum[BH];
__device__ float         g_psumsq[BH];
__device__ float         g_scale[H_DIM];
__device__ float         g_shift[H_DIM];
__device__ float         g_hlast[BH];

// ---------------- PTX helpers ----------------
__device__ __forceinline__ uint32_t smem_u32(const void* p) {
    uint32_t a;
    asm("{ .reg .u64 t; cvta.to.shared.u64 t, %1; cvt.u32.u64 %0, t; }" : "=r"(a) : "l"(p));
    return a;
}
__device__ __forceinline__ void cp16(uint32_t dst, const void* src) {
    asm volatile("cp.async.cg.shared.global [%0], [%1], 16;" :: "r"(dst), "l"(src));
}
#define CP_COMMIT() asm volatile("cp.async.commit_group;" ::: "memory")
#define CP_WAIT(n)  asm volatile("cp.async.wait_group %0;" :: "n"(n) : "memory")

__device__ __forceinline__ void ldsm4(uint32_t r[4], uint32_t addr) {
    asm volatile("ldmatrix.sync.aligned.m8n8.x4.shared.b16 {%0,%1,%2,%3}, [%4];"
        : "=r"(r[0]), "=r"(r[1]), "=r"(r[2]), "=r"(r[3]) : "r"(addr));
}
__device__ __forceinline__ void mma16816(float c[4], const uint32_t a[4],
                                         uint32_t b0, uint32_t b1) {
    asm volatile(
        "mma.sync.aligned.m16n8k16.row.col.f32.bf16.bf16.f32 "
        "{%0,%1,%2,%3}, {%4,%5,%6,%7}, {%8,%9}, {%0,%1,%2,%3};"
        : "+f"(c[0]), "+f"(c[1]), "+f"(c[2]), "+f"(c[3])
        : "r"(a[0]), "r"(a[1]), "r"(a[2]), "r"(a[3]), "r"(b0), "r"(b1));
}

// ---------------- tile loader: one KC chunk of Ah/Al/Bh/Bl ----------------
// stage layout: [Ah:0][Al:16K][Bh:32K][Bl:48K], each 128 rows x 128B, SW128 swizzle
__device__ __forceinline__ void load_chunk(
    int tid, uint32_t stage,
    const char* pAh, const char* pAl, const char* pBh, const char* pBl,
    long strideB, long k0b)
{
    const char* base[4] = {pAh, pAl, pBh, pBl};
    const int rbase = tid >> 3;
    const int cb    = (tid & 7) * 16;
    #pragma unroll
    for (int i = 0; i < 16; ++i) {
        const int arr = i >> 2;
        const int r   = (i & 3) * 32 + rbase;
        uint32_t off = (uint32_t)(r * 128 + cb);
        off ^= (off >> 3) & 0x70;
        cp16(stage + arr * TILE_BYTES + off, base[arr] + (long)r * strideB + k0b + cb);
    }
    CP_COMMIT();
}

// ---------------- GEMM: Z[m,n] = A@W^T + biasadj (3-product bf16 split) ----
__global__ __launch_bounds__(256, 1)
void gemm_mma(const __nv_bfloat16* __restrict__ Ah, const __nv_bfloat16* __restrict__ Al,
              const __nv_bfloat16* __restrict__ Bh, const __nv_bfloat16* __restrict__ Bl,
              const float* __restrict__ biasadj, float* __restrict__ Z, int K)
{
    extern __shared__ char dyn[];
    const uint32_t sbase = (smem_u32(dyn) + 1023u) & ~1023u;

    const int tid  = threadIdx.x;
    const int lane = tid & 31;
    const int wid  = tid >> 5;
    const int wm   = wid >> 2;            // 0..1  (m)
    const int wn   = wid & 3;             // 0..3  (n)
    const int n0   = blockIdx.x * BN;
    const int m0   = blockIdx.y * BM;
    const int NC   = K / KC;

    const long strideB = (long)K * 2;
    const char* pAh = (const char*)(Ah + (long)m0 * K);
    const char* pAl = (const char*)(Al + (long)m0 * K);
    const char* pBh = (const char*)(Bh + (long)n0 * K);
    const char* pBl = (const char*)(Bl + (long)n0 * K);

    // per-lane ldmatrix geometry (SW128: swz = row*128 + (col ^ ((row&7)<<4)))
    const int rowA  = wm * 64 + (lane & 15);            // + mi*16
    const int rowB  = wn * 32 + ((lane >> 4) << 3) + (lane & 7);  // + nj*16
    const int xorC  = (lane & 7) << 4;                  // row&7 == lane&7 for all rows
    const int colA0 = (lane >> 4) * 16;                 // + kk*32, then ^ xorC
    const int colB0 = ((lane >> 3) & 1) * 16;

    float acc[4][4][4];
    #pragma unroll
    for (int i = 0; i < 4; ++i)
        #pragma unroll
        for (int j = 0; j < 4; ++j)
            #pragma unroll
            for (int q = 0; q < 4; ++q) acc[i][j][q] = 0.0f;

    load_chunk(tid, sbase, pAh, pAl, pBh, pBl, strideB, 0);
    load_chunk(tid, sbase + STAGE_BYTES, pAh, pAl, pBh, pBl, strideB, (long)KC * 2);

    for (int c = 0; c < NC; ++c) {
        if (c + 1 < NC) { CP_WAIT(1); } else { CP_WAIT(0); }
        __syncthreads();
        if (c + 2 < NC)
            load_chunk(tid, sbase + ((c + 2) % NSTAGE) * STAGE_BYTES,
                       pAh, pAl, pBh, pBl, strideB, (long)(c + 2) * KC * 2);

        const uint32_t st  = sbase + (c % NSTAGE) * STAGE_BYTES;
        const uint32_t sAh = st;
        const uint32_t sAl = st + TILE_BYTES;
        const uint32_t sBh = st + 2 * TILE_BYTES;
        const uint32_t sBl = st + 3 * TILE_BYTES;

        #pragma unroll
        for (int kk = 0; kk < 4; ++kk) {
            const uint32_t cA = (uint32_t)((kk * 32 + colA0) ^ xorC);
            const uint32_t cB = (uint32_t)((kk * 32 + colB0) ^ xorC);
            uint32_t ah[4][4], al[4][4], bh[2][4], bl[2][4];
            #pragma unroll
            for (int mi = 0; mi < 4; ++mi) {
                ldsm4(ah[mi], sAh + (uint32_t)(rowA + mi * 16) * 128 + cA);
                ldsm4(al[mi], sAl + (uint32_t)(rowA + mi * 16) * 128 + cA);
            }
            #pragma unroll
            for (int nj = 0; nj < 2; ++nj) {
                ldsm4(bh[nj], sBh + (uint32_t)(rowB + nj * 16) * 128 + cB);
                ldsm4(bl[nj], sBl + (uint32_t)(rowB + nj * 16) * 128 + cB);
            }
            // product 1: Ah*Bh
            #pragma unroll
            for (int mi = 0; mi < 4; ++mi)
                #pragma unroll
                for (int ni = 0; ni < 4; ++ni)
                    mma16816(acc[mi][ni], ah[mi], bh[ni >> 1][(ni & 1) * 2], bh[ni >> 1][(ni & 1) * 2 + 1]);
            // product 2: Ah*Bl
            #pragma unroll
            for (int mi = 0; mi < 4; ++mi)
                #pragma unroll
                for (int ni = 0; ni < 4; ++ni)
                    mma16816(acc[mi][ni], ah[mi], bl[ni >> 1][(ni & 1) * 2], bl[ni >> 1][(ni & 1) * 2 + 1]);
            // product 3: Al*Bh
            #pragma unroll
            for (int mi = 0; mi < 4; ++mi)
                #pragma unroll
                for (int ni = 0; ni < 4; ++ni)
                    mma16816(acc[mi][ni], al[mi], bh[ni >> 1][(ni & 1) * 2], bh[ni >> 1][(ni & 1) * 2 + 1]);
        }
    }

    // epilogue: + bias, write fp32 Z
    const int g  = lane >> 2;
    const int tg = lane & 3;
    #pragma unroll
    for (int mi = 0; mi < 4; ++mi) {
        const int r0 = m0 + wm * 64 + mi * 16 + g;
        #pragma unroll
        for (int ni = 0; ni < 4; ++ni) {
            const int n = n0 + wn * 32 + ni * 8 + tg * 2;
            const float2 bia = *reinterpret_cast<const float2*>(&biasadj[n]);
            float2 v0 = {acc[mi][ni][0] + bia.x, acc[mi][ni][1] + bia.y};
            float2 v1 = {acc[mi][ni][2] + bia.x, acc[mi][ni][3] + bia.y};
            *reinterpret_cast<float2*>(&Z[(size_t)r0 * H_DIM + n])       = v0;
            *reinterpret_cast<float2*>(&Z[(size_t)(r0 + 8) * H_DIM + n]) = v1;
        }
    }
}

// ---------------- x -> padded split bf16 ----------------
__global__ __launch_bounds__(256)
void split_x(const float* __restrict__ x, __nv_bfloat16* __restrict__ xh,
             __nv_bfloat16* __restrict__ xl)
{
    const int idx = blockIdx.x * 256 + threadIdx.x;      // over MTOT*K0_PAD
    const int m = idx / K0_PAD, k = idx % K0_PAD;
    float v = (k < IN_RAW) ? x[m * IN_RAW + k] : 0.0f;
    __nv_bfloat16 hi = __float2bfloat16(v);
    xh[idx] = hi;
    xl[idx] = __float2bfloat16(v - __bfloat162float(hi));
}

// ---------------- layer-0 weights -> padded split ----------------
__global__ __launch_bounds__(256)
void prep_w0(const float* __restrict__ W0, const float* __restrict__ b0,
             __nv_bfloat16* __restrict__ Wh, __nv_bfloat16* __restrict__ Wl,
             float* __restrict__ biasadj)
{
    const int n = blockIdx.x;
    const int k = threadIdx.x;
    if (k < K0_PAD) {
        float v = (k < IN_RAW) ? W0[n * IN_RAW + k] : 0.0f;
        __nv_bfloat16 hi = __float2bfloat16(v);
        Wh[n * K0_PAD + k] = hi;
        Wl[n * K0_PAD + k] = __float2bfloat16(v - __bfloat162float(hi));
    }
    if (k == 0) biasadj[n] = b0[n];
}

// ---------------- layer l>=1 weights: fold BN affine -------------
// W'[n,k] = W[n,k]*scale[k];  biasadj[n] = b[n] + sum_k shift[k]*W[n,k]
__global__ __launch_bounds__(256)
void prep_w(const float* __restrict__ W, const float* __restrict__ scale,
            const float* __restrict__ shift, const float* __restrict__ bias_in,
            __nv_bfloat16* __restrict__ Wh, __nv_bfloat16* __restrict__ Wl,
            float* __restrict__ biasadj)
{
    const int n = blockIdx.x;
    const int tid = threadIdx.x;
    __shared__ float red[256];
    float s = 0.0f;
    #pragma unroll
    for (int i = 0; i < 8; ++i) {
        const int k = tid + i * 256;
        const float w = W[(size_t)n * H_DIM + k];
        const float ws = w * scale[k];
        __nv_bfloat16 hi = __float2bfloat16(ws);
        Wh[(size_t)n * H_DIM + k] = hi;
        Wl[(size_t)n * H_DIM + k] = __float2bfloat16(ws - __bfloat162float(hi));
        s = fmaf(shift[k], w, s);
    }
    red[tid] = s;
    __syncthreads();
    for (int off = 128; off > 0; off >>= 1) {
        if (tid < off) red[tid] += red[tid + off];
        __syncthreads();
    }
    if (tid == 0) biasadj[n] = bias_in[n] + red[0];
}

// ---------------- IndRNN scan -> split-bf16 h + stats ------------
__global__ __launch_bounds__(256)
void scan_kernel(const float* __restrict__ Z, const float* __restrict__ u,
                 __nv_bfloat16* __restrict__ Hh, __nv_bfloat16* __restrict__ Hl,
                 float* __restrict__ hlast,
                 float* __restrict__ psum, float* __restrict__ psumsq)
{
    const int j  = blockIdx.x * 256 + threadIdx.x;
    const float uh = u[j & (H_DIM - 1)];
    float hc = 0.0f, s = 0.0f, s2 = 0.0f;
    #pragma unroll 4
    for (int t = 0; t < T_DIM; ++t) {
        const float v = Z[(size_t)t * BH + j];
        hc = fmaxf(fmaf(uh, hc, v), 0.0f);
        __nv_bfloat16 hi = __float2bfloat16(hc);
        Hh[(size_t)t * BH + j] = hi;
        Hl[(size_t)t * BH + j] = __float2bfloat16(hc - __bfloat162float(hi));
        s += hc;
        s2 = fmaf(hc, hc, s2);
    }
    hlast[j]  = hc;
    psum[j]   = s;
    psumsq[j] = s2;
}

// ---------------- BN stats -> folded affine ----------------------
__global__ __launch_bounds__(256)
void bn_finalize(const float* __restrict__ psum, const float* __restrict__ psumsq,
                 const float* __restrict__ gamma, const float* __restrict__ beta,
                 float* __restrict__ scale, float* __restrict__ shift)
{
    const int h = blockIdx.x * 256 + threadIdx.x;
    float s = 0.0f, s2 = 0.0f;
    #pragma unroll 8
    for (int b = 0; b < B_DIM; ++b) {
        s  += psum[b * H_DIM + h];
        s2 += psumsq[b * H_DIM + h];
    }
    const float inv_n = 1.0f / (float)(T_DIM * B_DIM);
    const float mean  = s * inv_n;
    const float var   = s2 * inv_n - mean * mean;
    const float rstd  = rsqrtf(var + BN_EPS);
    const float sc    = gamma[h] * rstd;
    scale[h] = sc;
    shift[h] = fmaf(-mean, sc, beta[h]);
}

// ---------------- final projection -------------------------------
__global__ __launch_bounds__(256)
void final_proj(const float* __restrict__ Hlast,
                const float* __restrict__ scale, const float* __restrict__ shift,
                const float* __restrict__ Wl, const float* __restrict__ bl,
                float* __restrict__ out)
{
    const int b = blockIdx.x, c = blockIdx.y;
    __shared__ float red[256];
    float s = 0.0f;
    for (int h = threadIdx.x; h < H_DIM; h += 256) {
        const float hn = fmaf(Hlast[b * H_DIM + h], scale[h], shift[h]);
        s = fmaf(hn, Wl[c * H_DIM + h], s);
    }
    red[threadIdx.x] = s;
    __syncthreads();
    for (int off = 128; off > 0; off >>= 1) {
        if (threadIdx.x < off) red[threadIdx.x] += red[threadIdx.x + off];
        __syncthreads();
    }
    if (threadIdx.x == 0) out[b * C_DIM + c] = red[0] + bl[c];
}

// ---------------- launcher ---------------------------------------
extern "C" void kernel_launch(void* const* d_in, const int* in_sizes, int n_in,
                              void* d_out, int out_size)
{
    const float* x      = (const float*)d_in[0];
    const float* W0     = (const float*)d_in[1];
    const float* Ws     = (const float*)d_in[2];
    const float* bs     = (const float*)d_in[3];
    const float* us     = (const float*)d_in[4];
    const float* gammas = (const float*)d_in[5];
    const float* betas  = (const float*)d_in[6];
    const float* Wlast  = (const float*)d_in[7];
    const float* blast  = (const float*)d_in[8];
    float* out = (float*)d_out;

    float *z, *biasadj, *psum, *psumsq, *scale, *shift, *hlast;
    __nv_bfloat16 *ah, *al, *wh, *wl;
    cudaGetSymbolAddress((void**)&z,       g_z);
    cudaGetSymbolAddress((void**)&ah,      g_ah);
    cudaGetSymbolAddress((void**)&al,      g_al);
    cudaGetSymbolAddress((void**)&wh,      g_wh);
    cudaGetSymbolAddress((void**)&wl,      g_wl);
    cudaGetSymbolAddress((void**)&biasadj, g_biasadj);
    cudaGetSymbolAddress((void**)&psum,    g_psum);
    cudaGetSymbolAddress((void**)&psumsq,  g_psumsq);
    cudaGetSymbolAddress((void**)&scale,   g_scale);
    cudaGetSymbolAddress((void**)&shift,   g_shift);
    cudaGetSymbolAddress((void**)&hlast,   g_hlast);

    cudaFuncSetAttribute(gemm_mma, cudaFuncAttributeMaxDynamicSharedMemorySize, DSMEM_BYTES);

    const dim3 ggrid(H_DIM / BN, MTOT / BM);   // 16 x 64

    // ---- layer 0 ----
    split_x<<<(MTOT * K0_PAD) / 256, 256>>>(x, ah, al);
    prep_w0<<<H_DIM, 256>>>(W0, bs, wh, wl, biasadj);
    gemm_mma<<<ggrid, 256, DSMEM_BYTES>>>(ah, al, wh, wl, biasadj, z, K0_PAD);
    scan_kernel<<<BH / 256, 256>>>(z, us, ah, al, hlast, psum, psumsq);
    bn_finalize<<<H_DIM / 256, 256>>>(psum, psumsq, gammas, betas, scale, shift);

    // ---- layers 1..3 ----
    for (int l = 1; l < 4; ++l) {
        prep_w<<<H_DIM, 256>>>(Ws + (size_t)(l - 1) * H_DIM * H_DIM, scale, shift,
                               bs + l * H_DIM, wh, wl, biasadj);
        gemm_mma<<<ggrid, 256, DSMEM_BYTES>>>(ah, al, wh, wl, biasadj, z, H_DIM);
        scan_kernel<<<BH / 256, 256>>>(z, us + l * H_DIM, ah, al, hlast, psum, psumsq);
        bn_finalize<<<H_DIM / 256, 256>>>(psum, psumsq, gammas + l * H_DIM,
                                          betas + l * H_DIM, scale, shift);
    }

    final_proj<<<dim3(B_DIM, C_DIM), 256>>>(hlast, scale, shift, Wlast, blast, out);
}